// round 1
// baseline (speedup 1.0000x reference)
#include <cuda_runtime.h>

#define BB 256
#define TT 256
#define HH 16
#define DD 88
#define WSTRIDE 20   // padded h-stride: 44*20 % 32 == 16 -> the two d-halves use disjoint banks

// Scratch (no allocations allowed)
__device__ float g_W[4 * DD * WSTRIDE];          // W[(c*D+d)*20 + h]
__device__ float g_eexp[BB * TT * HH];           // exp(emit - m_e), 4 MB
__device__ float g_me[BB * TT];                  // per-(b,t) emit max
__device__ float g_part[BB];                     // per-batch log-likelihood

// ---------------------------------------------------------------------------
// K0: build the 4-way emission log table.
// c = 2*yprev + y.  val = y ? log(p[h,yprev,d]) : log1p(-p[h,yprev,d])
// ---------------------------------------------------------------------------
__global__ void k0_build_W(const float* __restrict__ probs_y) {
    for (int e = threadIdx.x; e < 4 * DD * HH; e += blockDim.x) {
        int h = e % HH;
        int rem = e / HH;
        int d = rem % DD;
        int c = rem / DD;
        int yp = c >> 1, yb = c & 1;
        float p = probs_y[(h * 2 + yp) * DD + d];
        float v = yb ? logf(p) : log1pf(-p);
        g_W[(c * DD + d) * WSTRIDE + h] = v;
    }
}

// ---------------------------------------------------------------------------
// K1: emit pass. One block = (batch b, 8 consecutive timesteps).
// Each warp handles one t: lane = (h, d-half); 44 table adds per lane.
// Stores eexp = exp(emit - max_h emit) and m_e.
// ---------------------------------------------------------------------------
__global__ void k1_emit(const float* __restrict__ seq, const int* __restrict__ lengths) {
    __shared__ float sW[4 * DD * WSTRIDE];   // 28160 B
    __shared__ int   soff[8][DD];            // precomputed word offsets (c*D+d)*20

    int b  = blockIdx.x;
    int t0 = blockIdx.y * 8;
    int L  = lengths[b];
    if (t0 >= L) return;                     // uniform per block

    int tid = threadIdx.x;
    for (int e = tid; e < 4 * DD * WSTRIDE; e += 256) sW[e] = g_W[e];

    for (int e = tid; e < 8 * DD; e += 256) {
        int ttl = e / DD, d = e % DD;
        int t = t0 + ttl;
        int code = 0;
        if (t < L) {
            float y  = seq[(b * TT + t) * DD + d];
            float yp = (t == 0) ? 0.f : seq[(b * TT + t - 1) * DD + d];
            code = (yp > 0.5f ? 2 : 0) + (y > 0.5f ? 1 : 0);
        }
        soff[ttl][d] = (code * DD + d) * WSTRIDE;
    }
    __syncthreads();

    int w = tid >> 5, lane = tid & 31;
    int t = t0 + w;
    if (t >= L) return;

    int h = lane & 15, half = lane >> 4;
    const int* offs = soff[w] + half * 44;
    float acc = 0.f;
#pragma unroll 4
    for (int k = 0; k < 44; k++)
        acc += sW[offs[k] + h];

    // combine the two d-halves -> every lane holds emit[lane&15]
    acc += __shfl_xor_sync(0xffffffffu, acc, 16);
    // max over the 16 states
    float m = acc;
    m = fmaxf(m, __shfl_xor_sync(0xffffffffu, m, 8));
    m = fmaxf(m, __shfl_xor_sync(0xffffffffu, m, 4));
    m = fmaxf(m, __shfl_xor_sync(0xffffffffu, m, 2));
    m = fmaxf(m, __shfl_xor_sync(0xffffffffu, m, 1));

    if (lane < 16) g_eexp[(b * TT + t) * HH + h] = __expf(acc - m);
    if (lane == 0) g_me[b * TT + t] = m;
}

// ---------------------------------------------------------------------------
// K2: sequential forward scan in scaled linear domain. One warp per batch.
//   a'_j = (sum_i a_i * P[i][j]) * eexp_t[j];   C += m_e[t]
// Renormalize by max every 8 steps. Masked tail contributes (T-L)*log(H).
// ---------------------------------------------------------------------------
__global__ void k2_scan(const int* __restrict__ lengths, const float* __restrict__ probs_x) {
    int b = blockIdx.x;
    int lane = threadIdx.x & 31;
    int j = lane & 15;                 // lanes 16..31 mirror lanes 0..15
    int L = lengths[b];

    float Pc[16];
#pragma unroll
    for (int i = 0; i < 16; i++) Pc[i] = probs_x[i * 16 + j];

    const float* eb = g_eexp + b * TT * HH;
    const float* mb = g_me + b * TT;

    // depth-4 prefetch pipeline (covers L2 latency in the serial loop)
    float ep[4], mp[4];
#pragma unroll
    for (int k = 0; k < 4; k++) {
        ep[k] = (k < L) ? eb[k * HH + j] : 1.f;
        mp[k] = (k < L) ? mb[k] : 0.f;
    }

    float a = (j == 0) ? 1.f : 0.f;    // alpha0 = one-hot state 0
    float C = 0.f;

    for (int t = 0; t < L; t++) {
        float ec = ep[t & 3], mc = mp[t & 3];
        int tn = t + 4;
        if (tn < L) {
            ep[t & 3] = __ldg(eb + tn * HH + j);
            mp[t & 3] = __ldg(mb + tn);
        }
        // mat-vec: split into two accumulators for ILP
        float a0 = 0.f, a1 = 0.f;
#pragma unroll
        for (int i = 0; i < 16; i += 2) {
            a0 = fmaf(__shfl_sync(0xffffffffu, a, i),     Pc[i],     a0);
            a1 = fmaf(__shfl_sync(0xffffffffu, a, i + 1), Pc[i + 1], a1);
        }
        a = (a0 + a1) * ec;
        C += mc;

        if ((t & 7) == 7) {            // periodic renorm
            float m = a;
            m = fmaxf(m, __shfl_xor_sync(0xffffffffu, m, 8));
            m = fmaxf(m, __shfl_xor_sync(0xffffffffu, m, 4));
            m = fmaxf(m, __shfl_xor_sync(0xffffffffu, m, 2));
            m = fmaxf(m, __shfl_xor_sync(0xffffffffu, m, 1));
            a /= m;
            C += logf(m);
        }
    }

    float s = a;
    s += __shfl_xor_sync(0xffffffffu, s, 8);
    s += __shfl_xor_sync(0xffffffffu, s, 4);
    s += __shfl_xor_sync(0xffffffffu, s, 2);
    s += __shfl_xor_sync(0xffffffffu, s, 1);

    float res = C + logf(s) + (float)(TT - L) * 2.7725887222397811f;  // log(16)
    if (threadIdx.x == 0) g_part[b] = res;
}

// ---------------------------------------------------------------------------
// K3: deterministic reduction of 256 per-batch results.
// ---------------------------------------------------------------------------
__global__ void k3_reduce(float* __restrict__ out) {
    __shared__ float sh[256];
    int tid = threadIdx.x;
    sh[tid] = g_part[tid];
    __syncthreads();
    for (int s = 128; s > 0; s >>= 1) {
        if (tid < s) sh[tid] += sh[tid + s];
        __syncthreads();
    }
    if (tid == 0) out[0] = sh[0];
}

// ---------------------------------------------------------------------------
extern "C" void kernel_launch(void* const* d_in, const int* in_sizes, int n_in,
                              void* d_out, int out_size) {
    const float* seq     = (const float*)d_in[0];  // (B,T,D) float32
    const int*   lengths = (const int*)  d_in[1];  // (B,)    int32
    const float* probs_x = (const float*)d_in[2];  // (H,H)   float32
    const float* probs_y = (const float*)d_in[3];  // (H,2,D) float32

    k0_build_W<<<1, 256>>>(probs_y);
    k1_emit<<<dim3(BB, TT / 8), 256>>>(seq, lengths);
    k2_scan<<<BB, 32>>>(lengths, probs_x);
    k3_reduce<<<1, 256>>>((float*)d_out);
}

// round 2
// speedup vs baseline: 2.5717x; 2.5717x over previous
#include <cuda_runtime.h>

#define BB 256
#define TT 256
#define HH 16
#define DD 88
#define LOG16F 2.7725887222397811f

__device__ float g_part[BB];
__device__ unsigned int g_ticket;   // zero-init; self-resets via atomicInc wrap

#define ACC16(P4)                                        \
    {                                                    \
        float4 v0 = (P4)[0], v1 = (P4)[1],               \
               v2 = (P4)[2], v3 = (P4)[3];               \
        acc[0] += v0.x;  acc[1] += v0.y;                 \
        acc[2] += v0.z;  acc[3] += v0.w;                 \
        acc[4] += v1.x;  acc[5] += v1.y;                 \
        acc[6] += v1.z;  acc[7] += v1.w;                 \
        acc[8] += v2.x;  acc[9] += v2.y;                 \
        acc[10] += v2.z; acc[11] += v2.w;                \
        acc[12] += v3.x; acc[13] += v3.y;                \
        acc[14] += v3.z; acc[15] += v3.w;                \
    }

#define DO_WORD(YW, PW, DBASE, CNT)                                          \
    {                                                                        \
        _Pragma("unroll 8")                                                  \
        for (int k = 0; k < (CNT); k++) {                                    \
            int code = ((((PW) >> k) & 1u) << 1) | (((YW) >> k) & 1u);       \
            const float4* p4 = reinterpret_cast<const float4*>(              \
                sTab + (((DBASE) + k) * 4 + code) * 20);                     \
            ACC16(p4);                                                       \
        }                                                                    \
    }

__global__ void __launch_bounds__(256, 4)
fused_hmm(const float* __restrict__ seq, const int* __restrict__ lengths,
          const float* __restrict__ px, const float* __restrict__ py,
          float* __restrict__ out) {
    // Shared: 28160 + 3084 + 16384 + 1024 = 48652 B (< 48 KB static limit)
    __shared__ __align__(16) float sTab[DD * 4 * 20];   // [(d*4+c)*20 + h]
    __shared__ unsigned sPack[(TT + 1) * 3];            // y bits, row t+1; row0 = 0
    __shared__ __align__(16) float sE[TT * HH];         // exp(emit - m)
    __shared__ float sMe[TT];                           // per-t emit max

    const int b = blockIdx.x;
    const int tid = threadIdx.x;
    const int lane = tid & 31;
    const int wid = tid >> 5;
    const int L = lengths[b];

    if (tid < 3) sPack[tid] = 0u;   // yprev row for t=0

    // ---- build emission log-table in SMEM (each block independently) ----
    for (int e = tid; e < 4 * DD * HH; e += 256) {
        int h = e & 15;
        int rem = e >> 4;
        int d = rem % DD;
        int c = rem / DD;
        int yp = c >> 1, yb = c & 1;
        float p = py[(h * 2 + yp) * DD + d];
        float v = yb ? logf(p) : log1pf(-p);
        sTab[(d * 4 + c) * 20 + h] = v;
    }

    // ---- bit-pack this batch's sequence: 3 words per timestep ----
    for (int q = wid; q < TT * 3; q += 8) {
        int t = q / 3;
        int ws = q - t * 3;
        int d = ws * 32 + lane;
        float y = (d < DD) ? seq[(b * TT + t) * DD + d] : 0.f;
        unsigned bits = __ballot_sync(0xffffffffu, y > 0.5f);
        if (lane == 0) sPack[(t + 1) * 3 + ws] = bits;
    }
    __syncthreads();

    // ---- emit pass: thread t computes emit[t, 0..15], exp-normalized ----
    {
        const int t = tid;
        if (t < L) {
            unsigned pw0 = sPack[t * 3 + 0], pw1 = sPack[t * 3 + 1], pw2 = sPack[t * 3 + 2];
            unsigned yw0 = sPack[t * 3 + 3], yw1 = sPack[t * 3 + 4], yw2 = sPack[t * 3 + 5];
            float acc[16];
#pragma unroll
            for (int h = 0; h < 16; h++) acc[h] = 0.f;

            DO_WORD(yw0, pw0, 0, 32);
            DO_WORD(yw1, pw1, 32, 32);
            DO_WORD(yw2, pw2, 64, 24);

            float m = acc[0];
#pragma unroll
            for (int h = 1; h < 16; h++) m = fmaxf(m, acc[h]);

            float4* eo = reinterpret_cast<float4*>(sE + t * 16);
#pragma unroll
            for (int h4 = 0; h4 < 4; h4++) {
                float4 ev;
                ev.x = __expf(acc[h4 * 4 + 0] - m);
                ev.y = __expf(acc[h4 * 4 + 1] - m);
                ev.z = __expf(acc[h4 * 4 + 2] - m);
                ev.w = __expf(acc[h4 * 4 + 3] - m);
                eo[h4] = ev;
            }
            sMe[t] = m;
        }
    }
    __syncthreads();

    // ---- serial forward scan in scaled linear domain (warp 0 only) ----
    if (wid == 0) {
        const int j = lane & 15;
        float Pc[16];
#pragma unroll
        for (int i = 0; i < 16; i++) Pc[i] = px[i * 16 + j];

        float a = (j == 0) ? 1.f : 0.f;   // alpha0 one-hot at state 0
        float C = 0.f;

        for (int t = 0; t < L; t++) {
            float ec = sE[t * 16 + j];
            float mc = sMe[t];
            float a0 = 0.f, a1 = 0.f;
#pragma unroll
            for (int i = 0; i < 16; i += 2) {
                a0 = fmaf(__shfl_sync(0xffffffffu, a, i),     Pc[i],     a0);
                a1 = fmaf(__shfl_sync(0xffffffffu, a, i + 1), Pc[i + 1], a1);
            }
            a = (a0 + a1) * ec;
            C += mc;

            if ((t & 7) == 7) {
                float m = a;
                m = fmaxf(m, __shfl_xor_sync(0xffffffffu, m, 8));
                m = fmaxf(m, __shfl_xor_sync(0xffffffffu, m, 4));
                m = fmaxf(m, __shfl_xor_sync(0xffffffffu, m, 2));
                m = fmaxf(m, __shfl_xor_sync(0xffffffffu, m, 1));
                a = __fdividef(a, m);
                C += logf(m);
            }
        }

        float s = a;
        s += __shfl_xor_sync(0xffffffffu, s, 8);
        s += __shfl_xor_sync(0xffffffffu, s, 4);
        s += __shfl_xor_sync(0xffffffffu, s, 2);
        s += __shfl_xor_sync(0xffffffffu, s, 1);

        float res = C + logf(s) + (float)(TT - L) * LOG16F;

        // ---- in-kernel deterministic final reduction (last block) ----
        unsigned lastFlag = 0;
        if (lane == 0) {
            g_part[b] = res;
            __threadfence();
            unsigned old = atomicInc(&g_ticket, BB - 1);   // wraps to 0 at 255
            lastFlag = (old == BB - 1) ? 1u : 0u;
        }
        lastFlag = __shfl_sync(0xffffffffu, lastFlag, 0);
        if (lastFlag) {
            __threadfence();
            float s2 = 0.f;
#pragma unroll
            for (int i = 0; i < BB / 32; i++)
                s2 += *((volatile float*)&g_part[i * 32 + lane]);
            s2 += __shfl_xor_sync(0xffffffffu, s2, 16);
            s2 += __shfl_xor_sync(0xffffffffu, s2, 8);
            s2 += __shfl_xor_sync(0xffffffffu, s2, 4);
            s2 += __shfl_xor_sync(0xffffffffu, s2, 2);
            s2 += __shfl_xor_sync(0xffffffffu, s2, 1);
            if (lane == 0) out[0] = s2;
        }
    }
}

extern "C" void kernel_launch(void* const* d_in, const int* in_sizes, int n_in,
                              void* d_out, int out_size) {
    const float* seq     = (const float*)d_in[0];  // (B,T,D) float32
    const int*   lengths = (const int*)  d_in[1];  // (B,)    int32
    const float* probs_x = (const float*)d_in[2];  // (H,H)   float32
    const float* probs_y = (const float*)d_in[3];  // (H,2,D) float32

    fused_hmm<<<BB, 256>>>(seq, lengths, probs_x, probs_y, (float*)d_out);
}

// round 3
// speedup vs baseline: 2.5820x; 1.0040x over previous
#include <cuda_runtime.h>

#define BB 256
#define TT 256
#define HH 16
#define DD 88
#define LOG16F 2.7725887222397811f

__device__ float g_part[BB];
__device__ unsigned int g_ticket;   // zero-init; self-resets via atomicInc wrap

#define ACC16(P4)                                        \
    {                                                    \
        float4 v0 = (P4)[0], v1 = (P4)[1],               \
               v2 = (P4)[2], v3 = (P4)[3];               \
        acc[0] += v0.x;  acc[1] += v0.y;                 \
        acc[2] += v0.z;  acc[3] += v0.w;                 \
        acc[4] += v1.x;  acc[5] += v1.y;                 \
        acc[6] += v1.z;  acc[7] += v1.w;                 \
        acc[8] += v2.x;  acc[9] += v2.y;                 \
        acc[10] += v2.z; acc[11] += v2.w;                \
        acc[12] += v3.x; acc[13] += v3.y;                \
        acc[14] += v3.z; acc[15] += v3.w;                \
    }

#define DO_WORD(YW, PW, DBASE, CNT)                                          \
    {                                                                        \
        _Pragma("unroll 8")                                                  \
        for (int k = 0; k < (CNT); k++) {                                    \
            int code = ((((PW) >> k) & 1u) << 1) | (((YW) >> k) & 1u);       \
            const float4* p4 = reinterpret_cast<const float4*>(              \
                sTab + (((DBASE) + k) * 4 + code) * 20);                     \
            ACC16(p4);                                                       \
        }                                                                    \
    }

__global__ void __launch_bounds__(256, 4)
fused_hmm(const float* __restrict__ seq, const int* __restrict__ lengths,
          const float* __restrict__ px, const float* __restrict__ py,
          float* __restrict__ out) {
    // Shared: 28160 + 3084 + 16384 + 1024 = 48652 B (< 48 KB static limit)
    __shared__ __align__(16) float sTab[DD * 4 * 20];   // [(d*4+c)*20 + h]
    __shared__ unsigned sPack[(TT + 1) * 3];            // y bits, row t+1; row0 = 0
    __shared__ __align__(16) float sE[TT * HH];         // exp(emit - m)
    __shared__ float sMe[TT];                           // per-t emit max

    const int b = blockIdx.x;
    const int tid = threadIdx.x;
    const int lane = tid & 31;
    const int wid = tid >> 5;
    const int L = lengths[b];

    if (tid < 3) sPack[tid] = 0u;   // yprev row for t=0

    // ---- build emission log-table in SMEM (each block independently) ----
    for (int e = tid; e < 4 * DD * HH; e += 256) {
        int h = e & 15;
        int rem = e >> 4;
        int d = rem % DD;
        int c = rem / DD;
        int yp = c >> 1, yb = c & 1;
        float p = py[(h * 2 + yp) * DD + d];
        float v = yb ? logf(p) : log1pf(-p);
        sTab[(d * 4 + c) * 20 + h] = v;
    }

    // ---- bit-pack this batch's sequence: 3 words per timestep ----
    for (int q = wid; q < TT * 3; q += 8) {
        int t = q / 3;
        int ws = q - t * 3;
        int d = ws * 32 + lane;
        float y = (d < DD) ? seq[(b * TT + t) * DD + d] : 0.f;
        unsigned bits = __ballot_sync(0xffffffffu, y > 0.5f);
        if (lane == 0) sPack[(t + 1) * 3 + ws] = bits;
    }
    __syncthreads();

    // ---- emit pass: thread t computes emit[t, 0..15], exp-normalized ----
    {
        const int t = tid;
        if (t < L) {
            unsigned pw0 = sPack[t * 3 + 0], pw1 = sPack[t * 3 + 1], pw2 = sPack[t * 3 + 2];
            unsigned yw0 = sPack[t * 3 + 3], yw1 = sPack[t * 3 + 4], yw2 = sPack[t * 3 + 5];
            float acc[16];
#pragma unroll
            for (int h = 0; h < 16; h++) acc[h] = 0.f;

            DO_WORD(yw0, pw0, 0, 32);
            DO_WORD(yw1, pw1, 32, 32);
            DO_WORD(yw2, pw2, 64, 24);

            float m = acc[0];
#pragma unroll
            for (int h = 1; h < 16; h++) m = fmaxf(m, acc[h]);

            float4* eo = reinterpret_cast<float4*>(sE + t * 16);
#pragma unroll
            for (int h4 = 0; h4 < 4; h4++) {
                float4 ev;
                ev.x = __expf(acc[h4 * 4 + 0] - m);
                ev.y = __expf(acc[h4 * 4 + 1] - m);
                ev.z = __expf(acc[h4 * 4 + 2] - m);
                ev.w = __expf(acc[h4 * 4 + 3] - m);
                eo[h4] = ev;
            }
            sMe[t] = m;
        }
    }
    __syncthreads();

    // ---- serial forward scan in scaled linear domain (warp 0 only) ----
    if (wid == 0) {
        const int j = lane & 15;
        float Pc[16];
#pragma unroll
        for (int i = 0; i < 16; i++) Pc[i] = px[i * 16 + j];

        float a = (j == 0) ? 1.f : 0.f;   // alpha0 one-hot at state 0
        float C = 0.f;

        for (int t = 0; t < L; t++) {
            float ec = sE[t * 16 + j];
            float mc = sMe[t];
            float a0 = 0.f, a1 = 0.f;
#pragma unroll
            for (int i = 0; i < 16; i += 2) {
                a0 = fmaf(__shfl_sync(0xffffffffu, a, i),     Pc[i],     a0);
                a1 = fmaf(__shfl_sync(0xffffffffu, a, i + 1), Pc[i + 1], a1);
            }
            a = (a0 + a1) * ec;
            C += mc;

            if ((t & 7) == 7) {
                float m = a;
                m = fmaxf(m, __shfl_xor_sync(0xffffffffu, m, 8));
                m = fmaxf(m, __shfl_xor_sync(0xffffffffu, m, 4));
                m = fmaxf(m, __shfl_xor_sync(0xffffffffu, m, 2));
                m = fmaxf(m, __shfl_xor_sync(0xffffffffu, m, 1));
                a = __fdividef(a, m);
                C += logf(m);
            }
        }

        float s = a;
        s += __shfl_xor_sync(0xffffffffu, s, 8);
        s += __shfl_xor_sync(0xffffffffu, s, 4);
        s += __shfl_xor_sync(0xffffffffu, s, 2);
        s += __shfl_xor_sync(0xffffffffu, s, 1);

        float res = C + logf(s) + (float)(TT - L) * LOG16F;

        // ---- in-kernel deterministic final reduction (last block) ----
        unsigned lastFlag = 0;
        if (lane == 0) {
            g_part[b] = res;
            __threadfence();
            unsigned old = atomicInc(&g_ticket, BB - 1);   // wraps to 0 at 255
            lastFlag = (old == BB - 1) ? 1u : 0u;
        }
        lastFlag = __shfl_sync(0xffffffffu, lastFlag, 0);
        if (lastFlag) {
            __threadfence();
            float s2 = 0.f;
#pragma unroll
            for (int i = 0; i < BB / 32; i++)
                s2 += *((volatile float*)&g_part[i * 32 + lane]);
            s2 += __shfl_xor_sync(0xffffffffu, s2, 16);
            s2 += __shfl_xor_sync(0xffffffffu, s2, 8);
            s2 += __shfl_xor_sync(0xffffffffu, s2, 4);
            s2 += __shfl_xor_sync(0xffffffffu, s2, 2);
            s2 += __shfl_xor_sync(0xffffffffu, s2, 1);
            if (lane == 0) out[0] = s2;
        }
    }
}

extern "C" void kernel_launch(void* const* d_in, const int* in_sizes, int n_in,
                              void* d_out, int out_size) {
    const float* seq     = (const float*)d_in[0];  // (B,T,D) float32
    const int*   lengths = (const int*)  d_in[1];  // (B,)    int32
    const float* probs_x = (const float*)d_in[2];  // (H,H)   float32
    const float* probs_y = (const float*)d_in[3];  // (H,2,D) float32

    fused_hmm<<<BB, 256>>>(seq, lengths, probs_x, probs_y, (float*)d_out);
}